// round 11
// baseline (speedup 1.0000x reference)
#include <cuda_runtime.h>

#define BATCH 8
#define HH 480
#define WW 640
#define PLANE (HH * WW)
#define NPIX (BATCH * PLANE)
#define TIMES 24
#define TFUSE 12
#define NLAUNCH (TIMES / TFUSE)   // 2

#define TILE_X 40
#define TILE_Y 40
#define OFF  11                   // inner tile: region rows 11..50, cols 12..51
#define NGRP 16                   // region cols 0..63; gx = ox-12 + grp*4
#define BROWS 64                  // buffer rows: region rows -1..62 (gy = oy-12+br)
#define BSTR 72                   // buffer col = region col + 4; ring at cols 3 / 68
#define NTHREADS 992              // 31 warps; warp = 2 rows x 16 groups
#define NF4 (BROWS * (BSTR / 4))  // 1152 float4s per buffer

// Scratch (allocation-free rule: __device__ globals)
__device__ float g_buf0[NPIX];
__device__ float g_buf1[NPIX];

// ---------------------------------------------------------------------------
__global__ void __launch_bounds__(NTHREADS, 1)
fused_kernel(const float* __restrict__ affinity,
             const float* __restrict__ fin, float* __restrict__ fout) {
    __shared__ __align__(16) float buf[2][BROWS * BSTR];

    const int tid  = threadIdx.x;
    const int lane = tid & 31;
    const int grp  = lane & 15;                       // col group 0..15
    const int row  = ((tid >> 5) << 1) + (lane >> 4); // region row 0..61
    const int ox = blockIdx.x * TILE_X;
    const int oy = blockIdx.y * TILE_Y;
    const int b  = blockIdx.z;

    const int gy  = oy - OFF + row;       // region row r <-> gy = oy-11+r
    const int gx0 = ox - 12 + grp * 4;    // 4-aligned

    const float4 z4 = make_float4(0.f, 0.f, 0.f, 0.f);

    // ---- issue all independent global loads up-front (MLP) ----
    const float* src = fin + (size_t)b * PLANE;
    const int br0 = tid / 18, bc40 = tid % 18;
    const int gyw0 = oy - 12 + br0, gxw0 = ox - 16 + bc40 * 4;
    float4 v0 = z4;
    if (gyw0 >= 0 && gyw0 < HH && gxw0 >= 0 && gxw0 < WW)
        v0 = __ldg((const float4*)(src + gyw0 * WW + gxw0));

    const int idx1 = tid + NTHREADS;
    const int br1 = idx1 / 18, bc41 = idx1 % 18;
    float4 v1 = z4;
    if (idx1 < NF4) {
        const int gyw1 = oy - 12 + br1, gxw1 = ox - 16 + bc41 * 4;
        if (gyw1 >= 0 && gyw1 < HH && gxw1 >= 0 && gxw1 < WW)
            v1 = __ldg((const float4*)(src + gyw1 * WW + gxw1));
    }

    // affinity: 8 float4 LDGs per thread (all groups within influence horizon)
    const bool ok = gy >= 0 && gy < HH && gx0 >= 0 && gx0 < WW;
    float4 a[8];
    {
        const float* ab = affinity + (size_t)b * 8 * PLANE + gy * WW + gx0;
#pragma unroll
        for (int c = 0; c < 8; c++)
            a[c] = ok ? __ldg((const float4*)(ab + (size_t)c * PLANE)) : z4;
    }

    // ---- store window: full buf0, ring-only buf1 ----
    ((float4*)&buf[0][br0 * BSTR])[bc40] = v0;
    if (br0 == 0 || br0 == BROWS - 1 || bc40 == 0 || bc40 == 17)
        ((float4*)&buf[1][br0 * BSTR])[bc40] = v0;
    if (idx1 < NF4) {
        ((float4*)&buf[0][br1 * BSTR])[bc41] = v1;
        if (br1 == 0 || br1 == BROWS - 1 || bc41 == 0 || bc41 == 17)
            ((float4*)&buf[1][br1 * BSTR])[bc41] = v1;
    }

    // ---- normalize -> 9 tap weights ----
    float4 w4[9];
    {
        float4 s = z4;
#pragma unroll
        for (int c = 0; c < 8; c++) {
            s.x += fabsf(a[c].x); s.y += fabsf(a[c].y);
            s.z += fabsf(a[c].z); s.w += fabsf(a[c].w);
        }
        const float4 inv = ok ? make_float4(1.f/s.x, 1.f/s.y, 1.f/s.z, 1.f/s.w) : z4;
        float4 ns = z4;
#pragma unroll
        for (int c = 0; c < 8; c++) {
            a[c].x *= inv.x; a[c].y *= inv.y;
            a[c].z *= inv.z; a[c].w *= inv.w;
            ns.x += a[c].x; ns.y += a[c].y;
            ns.z += a[c].z; ns.w += a[c].w;
        }
#pragma unroll
        for (int c = 0; c < 4; c++) w4[c] = a[c];
        w4[4] = ok ? make_float4(1.f - ns.x, 1.f - ns.y, 1.f - ns.z, 1.f - ns.w) : z4;
#pragma unroll
        for (int c = 4; c < 8; c++) w4[c + 1] = a[c];
    }

    __syncthreads();

    // ---- hoist static ring columns (never recomputed) ----
    const bool isL = (grp == 0), isR = (grp == 15);
    float ringL[3] = {0.f, 0.f, 0.f}, ringR[3] = {0.f, 0.f, 0.f};
    if (isL) {
#pragma unroll
        for (int r = 0; r < 3; r++) ringL[r] = buf[0][(row + r) * BSTR + 3];
    }
    if (isR) {
#pragma unroll
        for (int r = 0; r < 3; r++) ringR[r] = buf[0][(row + r) * BSTR + 68];
    }

    // ---- TFUSE fused iterations: 2 LDS.128 + carry + shfl ----
    const int bcol = grp * 4 + 4;
    float c0 = 0.f, c1 = 0.f, c2 = 0.f, c3 = 0.f;   // carried own-row values
    float a0, a1, a2, a3;
    int cur = 0;
#pragma unroll
    for (int t = 0; t < TFUSE; t++) {
        const float* s = buf[cur];
        const float4 r0 = *(const float4*)(s + row * BSTR + bcol);
        float4 r1;
        if (t == 0) r1 = *(const float4*)(s + (row + 1) * BSTR + bcol);
        else        r1 = make_float4(c0, c1, c2, c3);
        const float4 r2 = *(const float4*)(s + (row + 2) * BSTR + bcol);

        a0 = a1 = a2 = a3 = 0.f;
#pragma unroll
        for (int rr = 0; rr < 3; rr++) {
            const float4 rv = (rr == 0) ? r0 : (rr == 1) ? r1 : r2;
            float f0 = __shfl_up_sync(0xffffffffu, rv.w, 1);
            float f5 = __shfl_down_sync(0xffffffffu, rv.x, 1);
            if (isL) f0 = ringL[rr];
            if (isR) f5 = ringR[rr];
            const float4 wa = w4[3 * rr + 0];
            const float4 wb = w4[3 * rr + 1];
            const float4 wc = w4[3 * rr + 2];
            a0 = fmaf(wa.x, f0,   fmaf(wb.x, rv.x, fmaf(wc.x, rv.y, a0)));
            a1 = fmaf(wa.y, rv.x, fmaf(wb.y, rv.y, fmaf(wc.y, rv.z, a1)));
            a2 = fmaf(wa.z, rv.y, fmaf(wb.z, rv.z, fmaf(wc.z, rv.w, a2)));
            a3 = fmaf(wa.w, rv.z, fmaf(wb.w, rv.w, fmaf(wc.w, f5,   a3)));
        }
        c0 = a0; c1 = a1; c2 = a2; c3 = a3;
        if (t < TFUSE - 1) {
            *(float4*)(buf[cur ^ 1] + (row + 1) * BSTR + bcol) =
                make_float4(a0, a1, a2, a3);     // STS.128
            __syncthreads();
        }
        cur ^= 1;
    }

    // ---- final: inner 40x40 straight from registers (STG.128) ----
    if (row >= OFF && row < OFF + TILE_Y && grp >= 3 && grp < 13) {
        float* out = fout + (size_t)b * PLANE;
        *(float4*)(out + gy * WW + gx0) = make_float4(c0, c1, c2, c3);
    }
}

// ---------------------------------------------------------------------------
extern "C" void kernel_launch(void* const* d_in, const int* in_sizes, int n_in,
                              void* d_out, int out_size) {
    const float* affinity = (const float*)d_in[0];
    const float* feature  = (const float*)d_in[1];
    float* out = (float*)d_out;

    void* p0 = nullptr;
    cudaGetSymbolAddress(&p0, g_buf0);
    float* mid = (float*)p0;

    dim3 fblk(NTHREADS, 1, 1);
    dim3 fgrd(WW / TILE_X, HH / TILE_Y, BATCH);   // 16 x 12 x 8

    fused_kernel<<<fgrd, fblk>>>(affinity, feature, mid);
    fused_kernel<<<fgrd, fblk>>>(affinity, mid, out);
    (void)in_sizes; (void)n_in; (void)out_size;
}

// round 12
// speedup vs baseline: 1.1169x; 1.1169x over previous
#include <cuda_runtime.h>

#define BATCH 8
#define HH 480
#define WW 640
#define PLANE (HH * WW)
#define NPIX (BATCH * PLANE)
#define TIMES 24
#define TFUSE 8
#define NLAUNCH (TIMES / TFUSE)   // 3

#define TILE 48                   // inner tile 48x48
#define OFF  7                    // inner rows: region rows 7..54
#define ICOL0 8                   // inner cols: region cols 8..55 (groups 2..13)
#define NGRP 16                   // region cols 0..63; gx = ox-8 + grp*4
#define BROWS 64                  // buffer rows = region rows -1..62 (gy = oy-8+br)
#define BSTR 72                   // buffer col = region col + 4; ring at cols 3 / 68
#define NTHREADS 992              // 31 warps; warp = 2 rows x 16 groups
#define NF4 (BROWS * (BSTR / 4))  // 1152 float4s per buffer
#define GRIDX 14                  // 13 full tiles + 1 shifted (ox=592)

// Scratch (allocation-free rule: __device__ globals)
__device__ float g_buf0[NPIX];
__device__ float g_buf1[NPIX];

// ---------------------------------------------------------------------------
__global__ void __launch_bounds__(NTHREADS, 1)
fused_kernel(const float* __restrict__ affinity,
             const float* __restrict__ fin, float* __restrict__ fout) {
    __shared__ __align__(16) float buf[2][BROWS * BSTR];

    const int tid  = threadIdx.x;
    const int lane = tid & 31;
    const int grp  = lane & 15;                       // col group 0..15
    const int row  = ((tid >> 5) << 1) + (lane >> 4); // region row 0..61
    const int ox = (blockIdx.x < GRIDX - 1) ? blockIdx.x * TILE : (WW - TILE);
    const int oy = blockIdx.y * TILE;
    const int b  = blockIdx.z;

    const int gy  = oy - OFF + row;        // region row r <-> gy = oy-7+r
    const int gx0 = ox - ICOL0 + grp * 4;  // 4-aligned

    const float4 z4 = make_float4(0.f, 0.f, 0.f, 0.f);

    // ---- issue all independent global loads up-front (MLP) ----
    const float* src = fin + (size_t)b * PLANE;
    const int br0 = tid / 18, bc40 = tid % 18;
    const int gyw0 = oy - 8 + br0, gxw0 = ox - 12 + bc40 * 4;
    float4 v0 = z4;
    if (gyw0 >= 0 && gyw0 < HH && gxw0 >= 0 && gxw0 < WW)
        v0 = __ldg((const float4*)(src + gyw0 * WW + gxw0));

    const int idx1 = tid + NTHREADS;
    const int br1 = idx1 / 18, bc41 = idx1 % 18;
    float4 v1 = z4;
    if (idx1 < NF4) {
        const int gyw1 = oy - 8 + br1, gxw1 = ox - 12 + bc41 * 4;
        if (gyw1 >= 0 && gyw1 < HH && gxw1 >= 0 && gxw1 < WW)
            v1 = __ldg((const float4*)(src + gyw1 * WW + gxw1));
    }

    // affinity: 8 float4 LDGs per thread
    const bool ok = gy >= 0 && gy < HH && gx0 >= 0 && gx0 < WW;
    float4 a[8];
    {
        const float* ab = affinity + (size_t)b * 8 * PLANE + gy * WW + gx0;
#pragma unroll
        for (int c = 0; c < 8; c++)
            a[c] = ok ? __ldg((const float4*)(ab + (size_t)c * PLANE)) : z4;
    }

    // ---- store window: full buf0, ring-only buf1 ----
    ((float4*)&buf[0][br0 * BSTR])[bc40] = v0;
    if (br0 == 0 || br0 == BROWS - 1 || bc40 == 0 || bc40 == 17)
        ((float4*)&buf[1][br0 * BSTR])[bc40] = v0;
    if (idx1 < NF4) {
        ((float4*)&buf[0][br1 * BSTR])[bc41] = v1;
        if (br1 == 0 || br1 == BROWS - 1 || bc41 == 0 || bc41 == 17)
            ((float4*)&buf[1][br1 * BSTR])[bc41] = v1;
    }

    // ---- normalize -> 9 tap weights ----
    float4 w4[9];
    {
        float4 s = z4;
#pragma unroll
        for (int c = 0; c < 8; c++) {
            s.x += fabsf(a[c].x); s.y += fabsf(a[c].y);
            s.z += fabsf(a[c].z); s.w += fabsf(a[c].w);
        }
        const float4 inv = ok ? make_float4(1.f/s.x, 1.f/s.y, 1.f/s.z, 1.f/s.w) : z4;
        float4 ns = z4;
#pragma unroll
        for (int c = 0; c < 8; c++) {
            a[c].x *= inv.x; a[c].y *= inv.y;
            a[c].z *= inv.z; a[c].w *= inv.w;
            ns.x += a[c].x; ns.y += a[c].y;
            ns.z += a[c].z; ns.w += a[c].w;
        }
#pragma unroll
        for (int c = 0; c < 4; c++) w4[c] = a[c];
        w4[4] = ok ? make_float4(1.f - ns.x, 1.f - ns.y, 1.f - ns.z, 1.f - ns.w) : z4;
#pragma unroll
        for (int c = 4; c < 8; c++) w4[c + 1] = a[c];
    }

    __syncthreads();

    // ---- hoist static ring columns (never recomputed) ----
    const bool isL = (grp == 0), isR = (grp == 15);
    float ringL[3] = {0.f, 0.f, 0.f}, ringR[3] = {0.f, 0.f, 0.f};
    if (isL) {
#pragma unroll
        for (int r = 0; r < 3; r++) ringL[r] = buf[0][(row + r) * BSTR + 3];
    }
    if (isR) {
#pragma unroll
        for (int r = 0; r < 3; r++) ringR[r] = buf[0][(row + r) * BSTR + 68];
    }

    // ---- TFUSE fused iterations: 2 LDS.128 + carry + shfl ----
    const int bcol = grp * 4 + 4;
    float c0 = 0.f, c1 = 0.f, c2 = 0.f, c3 = 0.f;   // carried own-row values
    float a0, a1, a2, a3;
    int cur = 0;
#pragma unroll
    for (int t = 0; t < TFUSE; t++) {
        const float* s = buf[cur];
        const float4 r0 = *(const float4*)(s + row * BSTR + bcol);
        float4 r1;
        if (t == 0) r1 = *(const float4*)(s + (row + 1) * BSTR + bcol);
        else        r1 = make_float4(c0, c1, c2, c3);
        const float4 r2 = *(const float4*)(s + (row + 2) * BSTR + bcol);

        a0 = a1 = a2 = a3 = 0.f;
#pragma unroll
        for (int rr = 0; rr < 3; rr++) {
            const float4 rv = (rr == 0) ? r0 : (rr == 1) ? r1 : r2;
            float f0 = __shfl_up_sync(0xffffffffu, rv.w, 1);
            float f5 = __shfl_down_sync(0xffffffffu, rv.x, 1);
            if (isL) f0 = ringL[rr];
            if (isR) f5 = ringR[rr];
            const float4 wa = w4[3 * rr + 0];
            const float4 wb = w4[3 * rr + 1];
            const float4 wc = w4[3 * rr + 2];
            a0 = fmaf(wa.x, f0,   fmaf(wb.x, rv.x, fmaf(wc.x, rv.y, a0)));
            a1 = fmaf(wa.y, rv.x, fmaf(wb.y, rv.y, fmaf(wc.y, rv.z, a1)));
            a2 = fmaf(wa.z, rv.y, fmaf(wb.z, rv.z, fmaf(wc.z, rv.w, a2)));
            a3 = fmaf(wa.w, rv.z, fmaf(wb.w, rv.w, fmaf(wc.w, f5,   a3)));
        }
        c0 = a0; c1 = a1; c2 = a2; c3 = a3;
        if (t < TFUSE - 1) {
            *(float4*)(buf[cur ^ 1] + (row + 1) * BSTR + bcol) =
                make_float4(a0, a1, a2, a3);     // STS.128
            __syncthreads();
        }
        cur ^= 1;
    }

    // ---- final: inner 48x48 straight from registers (STG.128) ----
    if (row >= OFF && row < OFF + TILE && grp >= 2 && grp < 14) {
        float* out = fout + (size_t)b * PLANE;
        *(float4*)(out + gy * WW + gx0) = make_float4(c0, c1, c2, c3);
    }
}

// ---------------------------------------------------------------------------
extern "C" void kernel_launch(void* const* d_in, const int* in_sizes, int n_in,
                              void* d_out, int out_size) {
    const float* affinity = (const float*)d_in[0];
    const float* feature  = (const float*)d_in[1];
    float* out = (float*)d_out;

    void* p0 = nullptr; void* p1 = nullptr;
    cudaGetSymbolAddress(&p0, g_buf0);
    cudaGetSymbolAddress(&p1, g_buf1);
    float* buf[2] = { (float*)p0, (float*)p1 };

    dim3 fblk(NTHREADS, 1, 1);
    dim3 fgrd(GRIDX, HH / TILE, BATCH);   // 14 x 10 x 8

    const float* cursrc = feature;
    for (int l = 0; l < NLAUNCH; l++) {
        float* dst = (l == NLAUNCH - 1) ? out : buf[l & 1];
        fused_kernel<<<fgrd, fblk>>>(affinity, cursrc, dst);
        cursrc = dst;
    }
    (void)in_sizes; (void)n_in; (void)out_size;
}